// round 14
// baseline (speedup 1.0000x reference)
#include <cuda_runtime.h>
#include <cuda_bf16.h>

#define JNT 24
#define EPSF 1e-6f
#define SH_C0 0.28209479177387814f
#define SH_C1 0.4886025119029199f
#define C20 ( 1.0925484305920792f)
#define C21 (-1.0925484305920792f)
#define C22 ( 0.31539156525252005f)
#define C23 (-1.0925484305920792f)
#define C24 ( 0.5462742152960396f)

#define THREADS 256

__device__ __forceinline__ float frcp(float x) {
    float r; asm("rcp.approx.ftz.f32 %0, %1;" : "=f"(r) : "f"(x)); return r;
}

// Constant bank: 4 float4 per joint (geometry)
//  q0 : (-r00, -r01, -r02, L0-t0)
//  q1 : (-r10, -r11, -r12, L1-t1)
//  q2 : (-r20, -r21, -r22, L2-t2)
//  q3 : (t0, t1, t2, base)        base = SH_C0*f0 + 0.5 - C22*f6
__constant__ float4 cJ[JNT * 4];

// Global scratch for SH features (copied into shared per block)
//  s0 : (f1', f2', f3', f4')      pre-scaled SH features
//  s1 : (f5', f6'', f7', f8')     f6'' = 3*C22*f6
__device__ float4 gSH[JNT * 2];

__global__ void prep_kernel(float4* __restrict__ dst,
                            const float* __restrict__ T,
                            const float* __restrict__ F,
                            const float* __restrict__ L)
{
    const int t = threadIdx.x;
    if (t >= JNT * 6) return;
    const int j = t / 6, k = t % 6;
    float4 q;
    if (k < 3) {
        const float* r = T + j * 16 + k * 4;   // r0 r1 r2 t
        q = make_float4(-r[0], -r[1], -r[2], L[j * 3 + k] - r[3]);
    } else if (k == 3) {
        const float base = fmaf(SH_C0, F[j * 9 + 0], 0.5f) - C22 * F[j * 9 + 6];
        q = make_float4(T[j * 16 + 3], T[j * 16 + 7], T[j * 16 + 11], base);
    } else if (k == 4) {
        q = make_float4(-SH_C1 * F[j * 9 + 1],
                         SH_C1 * F[j * 9 + 2],
                        -SH_C1 * F[j * 9 + 3],
                         C20   * F[j * 9 + 4]);
    } else {
        q = make_float4( C21        * F[j * 9 + 5],
                         3.f * C22  * F[j * 9 + 6],
                         C23        * F[j * 9 + 7],
                         C24        * F[j * 9 + 8]);
    }
    if (k < 4) dst[j * 4 + k] = q;
    else       gSH[j * 2 + (k - 4)] = q;
}

__global__ __launch_bounds__(THREADS)
void shcaster_kernel(const float* __restrict__ xyz,
                     const float* __restrict__ vdir,
                     float* __restrict__ out,       // [2*N*3]
                     int N)
{
    __shared__ __align__(16) float4 sSH[JNT * 2];

    const int tid = threadIdx.x;
    if (tid < JNT * 2) sSH[tid] = gSH[tid];
    __syncthreads();

    const int i = blockIdx.x * blockDim.x + tid;
    if (i >= N) return;

    const float x0 = xyz[3 * i + 0];
    const float x1 = xyz[3 * i + 1];
    const float x2 = xyz[3 * i + 2];
    const float v0 = vdir[3 * i + 0];
    const float v1 = vdir[3 * i + 1];
    const float v2 = vdir[3 * i + 2];

    float wsum = 0.f;
    float ta0 = 0.f, ta1 = 0.f, ta2 = 0.f;            // sum w * t
    float m00 = 0.f, m01 = 0.f, m02 = 0.f;            // sum w * (-R)
    float m10 = 0.f, m11 = 0.f, m12 = 0.f;
    float m20 = 0.f, m21 = 0.f, m22 = 0.f;

#pragma unroll
    for (int j = 0; j < JNT; j++) {
        const float4 q0 = cJ[j * 4 + 0];
        const float4 q1 = cJ[j * 4 + 1];
        const float4 q2 = cJ[j * 4 + 2];
        const float4 q3 = cJ[j * 4 + 3];
        const float4 q4 = sSH[j * 2 + 0];
        const float4 q5 = sSH[j * 2 + 1];

        // d = (L - t) - R x  directly (negated R in table)
        const float d0 = fmaf(q0.x, x0, fmaf(q0.y, x1, fmaf(q0.z, x2, q0.w)));
        const float d1 = fmaf(q1.x, x0, fmaf(q1.y, x1, fmaf(q1.z, x2, q1.w)));
        const float d2 = fmaf(q2.x, x0, fmaf(q2.y, x1, fmaf(q2.z, x2, q2.w)));

        const float zz = d2 * d2;
        const float l2  = fmaf(d0, d0, fmaf(d1, d1, zz));
        const float inv = rsqrtf(l2);

        // SH dot in unnormalized d-space:
        // rad = ((quadD * inv + linD) * inv) + base
        const float linD = fmaf(q4.x, d1, fmaf(q4.y, d2, q4.z * d0));
        const float xy = d0 * d1;
        const float yz = d1 * d2;
        const float xz = d0 * d2;
        const float pm = fmaf(d0, d0, -(d1 * d1));   // x^2 - y^2
        const float quadD = fmaf(q4.w, xy,
                            fmaf(q5.x, yz,
                            fmaf(q5.y, zz,
                            fmaf(q5.z, xz, q5.w * pm))));
        const float tq  = fmaf(quadD, inv, linD);
        const float rad = fmaf(tq, inv, q3.w);

        // weight: r = max(relu(rad), EPS) = max(rad, EPS)
        const float r = fmaxf(rad, EPSF);
        const float len = l2 * inv;
        const float w = fmaxf(fmaf(-len, frcp(r), 1.0f), 0.f);

        wsum += w;
        ta0 = fmaf(w, q3.x, ta0);
        ta1 = fmaf(w, q3.y, ta1);
        ta2 = fmaf(w, q3.z, ta2);
        m00 = fmaf(w, q0.x, m00); m01 = fmaf(w, q0.y, m01); m02 = fmaf(w, q0.z, m02);
        m10 = fmaf(w, q1.x, m10); m11 = fmaf(w, q1.y, m11); m12 = fmaf(w, q1.z, m12);
        m20 = fmaf(w, q2.x, m20); m21 = fmaf(w, q2.y, m21); m22 = fmaf(w, q2.z, m22);
    }

    const float ic = frcp(fmaxf(wsum, EPSF));
    const bool valid = wsum > EPSF;

    // s = (sum w R) x + sum w t = tacc - (mneg x)
    const float mx0 = fmaf(m00, x0, fmaf(m01, x1, m02 * x2));
    const float mx1 = fmaf(m10, x0, fmaf(m11, x1, m12 * x2));
    const float mx2 = fmaf(m20, x0, fmaf(m21, x1, m22 * x2));
    const float o0 = valid ? (ta0 - mx0) * ic : x0;
    const float o1 = valid ? (ta1 - mx1) * ic : x1;
    const float o2 = valid ? (ta2 - mx2) * ic : x2;

    // vd_out = (mneg v) * (-ic)
    const float nic = -ic;
    const float e0 = fmaf(m00, v0, fmaf(m01, v1, m02 * v2)) * nic;
    const float e1 = fmaf(m10, v0, fmaf(m11, v1, m12 * v2)) * nic;
    const float e2 = fmaf(m20, v0, fmaf(m21, v1, m22 * v2)) * nic;
    const float g0 = valid ? e0 : v0;
    const float g1 = valid ? e1 : v1;
    const float g2 = valid ? e2 : v2;

    float* o1p = out + 3 * (size_t)i;
    float* o2p = out + 3 * ((size_t)N + i);
    o1p[0] = o0; o1p[1] = o1; o1p[2] = o2;
    o2p[0] = g0; o2p[1] = g1; o2p[2] = g2;
}

extern "C" void kernel_launch(void* const* d_in, const int* in_sizes, int n_in,
                              void* d_out, int out_size)
{
    const float* xyz  = (const float*)d_in[0];
    const float* vdir = (const float*)d_in[1];
    const float* T    = (const float*)d_in[2];
    const float* F    = (const float*)d_in[3];
    const float* L    = (const float*)d_in[4];
    float* out        = (float*)d_out;

    const int N = in_sizes[0] / 3;

    void* cjPtr = nullptr;
    cudaGetSymbolAddress(&cjPtr, cJ);
    prep_kernel<<<1, JNT * 6>>>((float4*)cjPtr, T, F, L);

    const int blocks = (N + THREADS - 1) / THREADS;
    shcaster_kernel<<<blocks, THREADS>>>(xyz, vdir, out, N);
}

// round 15
// speedup vs baseline: 1.1847x; 1.1847x over previous
#include <cuda_runtime.h>
#include <cuda_bf16.h>

#define JNT 24
#define EPSF 1e-6f
#define SH_C0 0.28209479177387814f
#define SH_C1 0.4886025119029199f
#define C20 ( 1.0925484305920792f)
#define C21 (-1.0925484305920792f)
#define C22 ( 0.31539156525252005f)
#define C23 (-1.0925484305920792f)
#define C24 ( 0.5462742152960396f)

#define THREADS 256

typedef unsigned long long u64;

__device__ __forceinline__ float frcp(float x) {
    float r; asm("rcp.approx.ftz.f32 %0, %1;" : "=f"(r) : "f"(x)); return r;
}
__device__ __forceinline__ u64 pkbc(float v) {   // broadcast pair {v,v}
    u64 r; asm("mov.b64 %0, {%1, %1};" : "=l"(r) : "f"(v)); return r;
}
__device__ __forceinline__ u64 pk2(float lo, float hi) {
    u64 r; asm("mov.b64 %0, {%1, %2};" : "=l"(r) : "f"(lo), "f"(hi)); return r;
}
__device__ __forceinline__ void upk2(float& lo, float& hi, u64 v) {
    asm("mov.b64 {%0, %1}, %2;" : "=f"(lo), "=f"(hi) : "l"(v));
}
__device__ __forceinline__ u64 ffma2(u64 a, u64 b, u64 c) {
    u64 d; asm("fma.rn.f32x2 %0, %1, %2, %3;" : "=l"(d) : "l"(a), "l"(b), "l"(c)); return d;
}

// Constant table: 6 float4 per joint — accumulated values form NATURAL pairs:
//  c0 : (-r00, -r01, -r02, t0)    pairs {-r00,-r01}, {-r02,t0}
//  c1 : (-r10, -r11, -r12, t1)    pairs {-r10,-r11}, {-r12,t1}
//  c2 : (-r20, -r21, -r22, t2)    pairs {-r20,-r21}, {-r22,t2}
//  c3 : (L0-t0, L1-t1, L2-t2, base)   base = SH_C0*f0 + 0.5 - C22*f6
//  c4 : (f1', f2', f3', f4')      pre-scaled SH features
//  c5 : (f5', f6'', f7', f8')     f6'' = 3*C22*f6
__constant__ float4 cJ[JNT * 6];

__global__ void prep_kernel(float4* __restrict__ dst,
                            const float* __restrict__ T,
                            const float* __restrict__ F,
                            const float* __restrict__ L)
{
    const int t = threadIdx.x;
    if (t >= JNT * 6) return;
    const int j = t / 6, k = t % 6;
    float4 q;
    if (k < 3) {
        const float* r = T + j * 16 + k * 4;   // r0 r1 r2 t
        q = make_float4(-r[0], -r[1], -r[2], r[3]);
    } else if (k == 3) {
        const float base = fmaf(SH_C0, F[j * 9 + 0], 0.5f) - C22 * F[j * 9 + 6];
        q = make_float4(L[j * 3 + 0] - T[j * 16 + 3],
                        L[j * 3 + 1] - T[j * 16 + 7],
                        L[j * 3 + 2] - T[j * 16 + 11],
                        base);
    } else if (k == 4) {
        q = make_float4(-SH_C1 * F[j * 9 + 1],
                         SH_C1 * F[j * 9 + 2],
                        -SH_C1 * F[j * 9 + 3],
                         C20   * F[j * 9 + 4]);
    } else {
        q = make_float4( C21        * F[j * 9 + 5],
                         3.f * C22  * F[j * 9 + 6],
                         C23        * F[j * 9 + 7],
                         C24        * F[j * 9 + 8]);
    }
    dst[j * 6 + k] = q;
}

__global__ __launch_bounds__(THREADS)
void shcaster_kernel(const float* __restrict__ xyz,
                     const float* __restrict__ vdir,
                     float* __restrict__ out,       // [2*N*3]
                     int N)
{
    const int i = blockIdx.x * blockDim.x + threadIdx.x;
    if (i >= N) return;

    const float x0 = xyz[3 * i + 0];
    const float x1 = xyz[3 * i + 1];
    const float x2 = xyz[3 * i + 2];
    const float v0 = vdir[3 * i + 0];
    const float v1 = vdir[3 * i + 1];
    const float v2 = vdir[3 * i + 2];

    float wsum = 0.f;
    u64 A0 = 0ull;   // {m00, m01}    m = sum w * (-R)
    u64 A1 = 0ull;   // {m02, ta0}    ta = sum w * t
    u64 A2 = 0ull;   // {m10, m11}
    u64 A3 = 0ull;   // {m12, ta1}
    u64 A4 = 0ull;   // {m20, m21}
    u64 A5 = 0ull;   // {m22, ta2}

#pragma unroll
    for (int j = 0; j < JNT; j++) {
        const float4 c0 = cJ[j * 6 + 0];
        const float4 c1 = cJ[j * 6 + 1];
        const float4 c2 = cJ[j * 6 + 2];
        const float4 c3 = cJ[j * 6 + 3];
        const float4 c4 = cJ[j * 6 + 4];
        const float4 c5 = cJ[j * 6 + 5];

        // d = (L - t) - R x  (negated R, addend from c3)
        const float d0 = fmaf(c0.x, x0, fmaf(c0.y, x1, fmaf(c0.z, x2, c3.x)));
        const float d1 = fmaf(c1.x, x0, fmaf(c1.y, x1, fmaf(c1.z, x2, c3.y)));
        const float d2 = fmaf(c2.x, x0, fmaf(c2.y, x1, fmaf(c2.z, x2, c3.z)));

        const float zz = d2 * d2;
        const float l2  = fmaf(d0, d0, fmaf(d1, d1, zz));
        const float inv = rsqrtf(l2);

        // SH dot in unnormalized d-space: rad = ((quad*inv + lin)*inv) + base
        const float linD = fmaf(c4.x, d1, fmaf(c4.y, d2, c4.z * d0));
        const float xy = d0 * d1;
        const float yz = d1 * d2;
        const float xz = d0 * d2;
        const float pm = fmaf(d0, d0, -(d1 * d1));   // x^2 - y^2
        const float quadD = fmaf(c4.w, xy,
                            fmaf(c5.x, yz,
                            fmaf(c5.y, zz,
                            fmaf(c5.z, xz, c5.w * pm))));
        const float rad = fmaf(fmaf(quadD, inv, linD), inv, c3.w);

        // weight: r = max(relu(rad), EPS) = max(rad, EPS)
        const float r = fmaxf(rad, EPSF);
        const float len = l2 * inv;
        const float w = fmaxf(fmaf(-len, frcp(r), 1.0f), 0.f);

        wsum += w;
        const u64 ww = pkbc(w);
        A0 = ffma2(ww, pk2(c0.x, c0.y), A0);
        A1 = ffma2(ww, pk2(c0.z, c0.w), A1);
        A2 = ffma2(ww, pk2(c1.x, c1.y), A2);
        A3 = ffma2(ww, pk2(c1.z, c1.w), A3);
        A4 = ffma2(ww, pk2(c2.x, c2.y), A4);
        A5 = ffma2(ww, pk2(c2.z, c2.w), A5);
    }

    float m00, m01, m02, m10, m11, m12, m20, m21, m22, ta0, ta1, ta2;
    upk2(m00, m01, A0);
    upk2(m02, ta0, A1);
    upk2(m10, m11, A2);
    upk2(m12, ta1, A3);
    upk2(m20, m21, A4);
    upk2(m22, ta2, A5);

    const float ic = frcp(fmaxf(wsum, EPSF));
    const bool valid = wsum > EPSF;

    // s = (sum w R) x + sum w t = tacc - (mneg x)
    const float mx0 = fmaf(m00, x0, fmaf(m01, x1, m02 * x2));
    const float mx1 = fmaf(m10, x0, fmaf(m11, x1, m12 * x2));
    const float mx2 = fmaf(m20, x0, fmaf(m21, x1, m22 * x2));
    const float o0 = valid ? (ta0 - mx0) * ic : x0;
    const float o1 = valid ? (ta1 - mx1) * ic : x1;
    const float o2 = valid ? (ta2 - mx2) * ic : x2;

    // vd_out = (mneg v) * (-ic)
    const float nic = -ic;
    const float e0 = fmaf(m00, v0, fmaf(m01, v1, m02 * v2)) * nic;
    const float e1 = fmaf(m10, v0, fmaf(m11, v1, m12 * v2)) * nic;
    const float e2 = fmaf(m20, v0, fmaf(m21, v1, m22 * v2)) * nic;
    const float g0 = valid ? e0 : v0;
    const float g1 = valid ? e1 : v1;
    const float g2 = valid ? e2 : v2;

    float* o1p = out + 3 * (size_t)i;
    float* o2p = out + 3 * ((size_t)N + i);
    o1p[0] = o0; o1p[1] = o1; o1p[2] = o2;
    o2p[0] = g0; o2p[1] = g1; o2p[2] = g2;
}

extern "C" void kernel_launch(void* const* d_in, const int* in_sizes, int n_in,
                              void* d_out, int out_size)
{
    const float* xyz  = (const float*)d_in[0];
    const float* vdir = (const float*)d_in[1];
    const float* T    = (const float*)d_in[2];
    const float* F    = (const float*)d_in[3];
    const float* L    = (const float*)d_in[4];
    float* out        = (float*)d_out;

    const int N = in_sizes[0] / 3;

    void* cjPtr = nullptr;
    cudaGetSymbolAddress(&cjPtr, cJ);
    prep_kernel<<<1, JNT * 6>>>((float4*)cjPtr, T, F, L);

    const int blocks = (N + THREADS - 1) / THREADS;
    shcaster_kernel<<<blocks, THREADS>>>(xyz, vdir, out, N);
}

// round 16
// speedup vs baseline: 1.2027x; 1.0152x over previous
#include <cuda_runtime.h>
#include <cuda_bf16.h>

#define JNT 24
#define EPSF 1e-6f
#define SH_C0 0.28209479177387814f
#define SH_C1 0.4886025119029199f
#define C20 ( 1.0925484305920792f)
#define C21 (-1.0925484305920792f)
#define C22 ( 0.31539156525252005f)
#define C23 (-1.0925484305920792f)
#define C24 ( 0.5462742152960396f)

#define THREADS 256

typedef unsigned long long u64;

__device__ __forceinline__ float frcp(float x) {
    float r; asm("rcp.approx.ftz.f32 %0, %1;" : "=f"(r) : "f"(x)); return r;
}
__device__ __forceinline__ u64 pkbc(float v) {   // broadcast pair {v,v}
    u64 r; asm("mov.b64 %0, {%1, %1};" : "=l"(r) : "f"(v)); return r;
}
__device__ __forceinline__ u64 pk2(float lo, float hi) {
    u64 r; asm("mov.b64 %0, {%1, %2};" : "=l"(r) : "f"(lo), "f"(hi)); return r;
}
__device__ __forceinline__ void upk2(float& lo, float& hi, u64 v) {
    asm("mov.b64 {%0, %1}, %2;" : "=f"(lo), "=f"(hi) : "l"(v));
}
__device__ __forceinline__ u64 ffma2(u64 a, u64 b, u64 c) {
    u64 d; asm("fma.rn.f32x2 %0, %1, %2, %3;" : "=l"(d) : "l"(a), "l"(b), "l"(c)); return d;
}

// Constant table: 6 float4 per joint — accumulated values form NATURAL pairs:
//  c0 : (-r00, -r01, -r02, t0)    pairs {-r00,-r01}, {-r02,t0}
//  c1 : (-r10, -r11, -r12, t1)    pairs {-r10,-r11}, {-r12,t1}
//  c2 : (-r20, -r21, -r22, t2)    pairs {-r20,-r21}, {-r22,t2}
//  c3 : (L0-t0, L1-t1, L2-t2, base)   base = SH_C0*f0 + 0.5 - C22*f6
//  c4 : (f1', f2', f3', f4')      pre-scaled SH features
//  c5 : (f5', f6'', f7', f8')     f6'' = 3*C22*f6
__constant__ float4 cJ[JNT * 6];

__global__ void prep_kernel(float4* __restrict__ dst,
                            const float* __restrict__ T,
                            const float* __restrict__ F,
                            const float* __restrict__ L)
{
    const int t = threadIdx.x;
    if (t >= JNT * 6) return;
    const int j = t / 6, k = t % 6;
    float4 q;
    if (k < 3) {
        const float* r = T + j * 16 + k * 4;   // r0 r1 r2 t
        q = make_float4(-r[0], -r[1], -r[2], r[3]);
    } else if (k == 3) {
        const float base = fmaf(SH_C0, F[j * 9 + 0], 0.5f) - C22 * F[j * 9 + 6];
        q = make_float4(L[j * 3 + 0] - T[j * 16 + 3],
                        L[j * 3 + 1] - T[j * 16 + 7],
                        L[j * 3 + 2] - T[j * 16 + 11],
                        base);
    } else if (k == 4) {
        q = make_float4(-SH_C1 * F[j * 9 + 1],
                         SH_C1 * F[j * 9 + 2],
                        -SH_C1 * F[j * 9 + 3],
                         C20   * F[j * 9 + 4]);
    } else {
        q = make_float4( C21        * F[j * 9 + 5],
                         3.f * C22  * F[j * 9 + 6],
                         C23        * F[j * 9 + 7],
                         C24        * F[j * 9 + 8]);
    }
    dst[j * 6 + k] = q;
}

__global__ __launch_bounds__(THREADS, 7)
void shcaster_kernel(const float* __restrict__ xyz,
                     const float* __restrict__ vdir,
                     float* __restrict__ out,       // [2*N*3]
                     int N)
{
    const int i = blockIdx.x * blockDim.x + threadIdx.x;
    if (i >= N) return;

    const float x0 = xyz[3 * i + 0];
    const float x1 = xyz[3 * i + 1];
    const float x2 = xyz[3 * i + 2];
    const float v0 = vdir[3 * i + 0];
    const float v1 = vdir[3 * i + 1];
    const float v2 = vdir[3 * i + 2];

    float wsum = 0.f;
    u64 A0 = 0ull;   // {m00, m01}    m = sum w * (-R)
    u64 A1 = 0ull;   // {m02, ta0}    ta = sum w * t
    u64 A2 = 0ull;   // {m10, m11}
    u64 A3 = 0ull;   // {m12, ta1}
    u64 A4 = 0ull;   // {m20, m21}
    u64 A5 = 0ull;   // {m22, ta2}

#pragma unroll
    for (int j = 0; j < JNT; j++) {
        const float4 c0 = cJ[j * 6 + 0];
        const float4 c1 = cJ[j * 6 + 1];
        const float4 c2 = cJ[j * 6 + 2];
        const float4 c3 = cJ[j * 6 + 3];
        const float4 c4 = cJ[j * 6 + 4];
        const float4 c5 = cJ[j * 6 + 5];

        // d = (L - t) - R x  (negated R, addend from c3)
        const float d0 = fmaf(c0.x, x0, fmaf(c0.y, x1, fmaf(c0.z, x2, c3.x)));
        const float d1 = fmaf(c1.x, x0, fmaf(c1.y, x1, fmaf(c1.z, x2, c3.y)));
        const float d2 = fmaf(c2.x, x0, fmaf(c2.y, x1, fmaf(c2.z, x2, c3.z)));

        const float zz = d2 * d2;
        const float l2  = fmaf(d0, d0, fmaf(d1, d1, zz));
        const float inv = rsqrtf(l2);

        // SH dot in unnormalized d-space: rad = ((quad*inv + lin)*inv) + base
        const float linD = fmaf(c4.x, d1, fmaf(c4.y, d2, c4.z * d0));
        const float xy = d0 * d1;
        const float yz = d1 * d2;
        const float xz = d0 * d2;
        const float pm = fmaf(d0, d0, -(d1 * d1));   // x^2 - y^2
        const float quadD = fmaf(c4.w, xy,
                            fmaf(c5.x, yz,
                            fmaf(c5.y, zz,
                            fmaf(c5.z, xz, c5.w * pm))));
        const float rad = fmaf(fmaf(quadD, inv, linD), inv, c3.w);

        // weight: r = max(relu(rad), EPS) = max(rad, EPS)
        const float r = fmaxf(rad, EPSF);
        const float len = l2 * inv;
        const float w = fmaxf(fmaf(-len, frcp(r), 1.0f), 0.f);

        wsum += w;
        const u64 ww = pkbc(w);
        A0 = ffma2(ww, pk2(c0.x, c0.y), A0);
        A1 = ffma2(ww, pk2(c0.z, c0.w), A1);
        A2 = ffma2(ww, pk2(c1.x, c1.y), A2);
        A3 = ffma2(ww, pk2(c1.z, c1.w), A3);
        A4 = ffma2(ww, pk2(c2.x, c2.y), A4);
        A5 = ffma2(ww, pk2(c2.z, c2.w), A5);
    }

    float m00, m01, m02, m10, m11, m12, m20, m21, m22, ta0, ta1, ta2;
    upk2(m00, m01, A0);
    upk2(m02, ta0, A1);
    upk2(m10, m11, A2);
    upk2(m12, ta1, A3);
    upk2(m20, m21, A4);
    upk2(m22, ta2, A5);

    const float ic = frcp(fmaxf(wsum, EPSF));
    const bool valid = wsum > EPSF;

    // s = (sum w R) x + sum w t = tacc - (mneg x)
    const float mx0 = fmaf(m00, x0, fmaf(m01, x1, m02 * x2));
    const float mx1 = fmaf(m10, x0, fmaf(m11, x1, m12 * x2));
    const float mx2 = fmaf(m20, x0, fmaf(m21, x1, m22 * x2));
    const float o0 = valid ? (ta0 - mx0) * ic : x0;
    const float o1 = valid ? (ta1 - mx1) * ic : x1;
    const float o2 = valid ? (ta2 - mx2) * ic : x2;

    // vd_out = (mneg v) * (-ic)
    const float nic = -ic;
    const float e0 = fmaf(m00, v0, fmaf(m01, v1, m02 * v2)) * nic;
    const float e1 = fmaf(m10, v0, fmaf(m11, v1, m12 * v2)) * nic;
    const float e2 = fmaf(m20, v0, fmaf(m21, v1, m22 * v2)) * nic;
    const float g0 = valid ? e0 : v0;
    const float g1 = valid ? e1 : v1;
    const float g2 = valid ? e2 : v2;

    float* o1p = out + 3 * (size_t)i;
    float* o2p = out + 3 * ((size_t)N + i);
    o1p[0] = o0; o1p[1] = o1; o1p[2] = o2;
    o2p[0] = g0; o2p[1] = g1; o2p[2] = g2;
}

extern "C" void kernel_launch(void* const* d_in, const int* in_sizes, int n_in,
                              void* d_out, int out_size)
{
    const float* xyz  = (const float*)d_in[0];
    const float* vdir = (const float*)d_in[1];
    const float* T    = (const float*)d_in[2];
    const float* F    = (const float*)d_in[3];
    const float* L    = (const float*)d_in[4];
    float* out        = (float*)d_out;

    const int N = in_sizes[0] / 3;

    void* cjPtr = nullptr;
    cudaGetSymbolAddress(&cjPtr, cJ);
    prep_kernel<<<1, JNT * 6>>>((float4*)cjPtr, T, F, L);

    const int blocks = (N + THREADS - 1) / THREADS;
    shcaster_kernel<<<blocks, THREADS>>>(xyz, vdir, out, N);
}